// round 12
// baseline (speedup 1.0000x reference)
#include <cuda_runtime.h>
#include <cstdint>

#define GD 256
#define GH 256
#define GW 256
#define RWIN 6
#define DHW_I 16777216
#define NT8 32             // 8^3 tiles per axis
#define NTILE8 32768       // 32^3 tiles
#define CAP8 64            // pairs per bucket (lambda ~7)
#define MAXN 32768

// zero-initialized at module load; splat resets cursors each replay
__device__ int    g_cursors8[NTILE8];
__device__ uint2  g_pairs8 [NTILE8 * CAP8];   // 16 MB scratch
__device__ float4 g_params [MAXN * 3];  // {cx,cy,cz,C00},{C11,C22,S01,S02},{S12,wr,wi,-}

// ---------------------------------------------------------------------------
__device__ __forceinline__ bool gbounds(float cx, float cy, float cz, float r,
                                        int& x0, int& x1, int& y0, int& y1,
                                        int& z0, int& z1)
{
    const int bx = (int)floorf(cx);
    const int by = (int)floorf(cy);
    const int bz = (int)floorf(cz);
    x0 = max((int)floorf(cx - r), max(bx - RWIN, 0));
    x1 = min((int)ceilf (cx + r), min(bx + RWIN, GD - 1));
    y0 = max((int)floorf(cy - r), max(by - RWIN, 0));
    y1 = min((int)ceilf (cy + r), min(by + RWIN, GH - 1));
    z0 = max((int)floorf(cz - r), max(bz - RWIN, 0));
    z1 = min((int)ceilf (cz + r), min(bz + RWIN, GW - 1));
    return (x0 <= x1) && (y0 <= y1) && (z0 <= z1);
}

// ---------------------------------------------------------------------------
// Binning into 8^3-tile buckets + param packing.
// pr.x = gid;  pr.y = tile-local bounds lx0,lx1,ly0,ly1,lz0,lz1 (4b fields).
// ---------------------------------------------------------------------------
__global__ __launch_bounds__(64)
void scatter_kernel(const float* __restrict__ center,
                    const float* __restrict__ covinv,
                    const float* __restrict__ dens_r,
                    const float* __restrict__ dens_i,
                    const float* __restrict__ radius, int N)
{
    int g = blockIdx.x * blockDim.x + threadIdx.x;
    if (g >= N) return;

    const float cx = center[3*g+0], cy = center[3*g+1], cz = center[3*g+2];

    g_params[3*g+0] = make_float4(cx, cy, cz, covinv[9*g+0]);
    g_params[3*g+1] = make_float4(covinv[9*g+4], covinv[9*g+8],
                                  covinv[9*g+1] + covinv[9*g+3],
                                  covinv[9*g+2] + covinv[9*g+6]);
    g_params[3*g+2] = make_float4(covinv[9*g+5] + covinv[9*g+7],
                                  dens_r[g], dens_i[g], 0.0f);

    int x0, x1, y0, y1, z0, z1;
    if (!gbounds(cx, cy, cz, radius[g], x0, x1, y0, y1, z0, z1)) return;

    for (int tx = x0 >> 3; tx <= (x1 >> 3); ++tx) {
        const int xb = tx * 8;
        const unsigned lx0 = (unsigned)max(x0 - xb, 0);
        const unsigned lx1 = (unsigned)min(x1 - xb, 7);
        for (int ty = y0 >> 3; ty <= (y1 >> 3); ++ty) {
            const int yb = ty * 8;
            const unsigned ly0 = (unsigned)max(y0 - yb, 0);
            const unsigned ly1 = (unsigned)min(y1 - yb, 7);
            for (int tz = z0 >> 3; tz <= (z1 >> 3); ++tz) {
                const int zb = tz * 8;
                const unsigned lz0 = (unsigned)max(z0 - zb, 0);
                const unsigned lz1 = (unsigned)min(z1 - zb, 7);
                const unsigned bb = lx0 | (lx1 << 4) | (ly0 << 8) |
                                    (ly1 << 12) | (lz0 << 16) | (lz1 << 20);
                const int tile = (tx * NT8 + ty) * NT8 + tz;
                const int slot = atomicAdd(&g_cursors8[tile], 1);
                if (slot < CAP8)
                    g_pairs8[tile * CAP8 + slot] = make_uint2((unsigned)g, bb);
            }
        }
    }
}

// ---------------------------------------------------------------------------
// One 256-thread CTA per 8x8x64 z-slab; each WARP exclusively owns one 8^3
// tile (4 KB smem float4 accumulator, z-paired). Exactly ONE warp engages per
// pair -> no cross-warp skip scans, no staging, no __syncthreads in the loop.
//  * 64 xy cells = 2 lane-blocks (x 0-3 / x 4-7), warp-uniform block skip
//  * xy mask folded into wr/wi (FSEL once per pair)
//  * R9-validated interleaved log2-domain forward-difference z chains
//  * ex2.approx.ftz(-1000) == +0.0f performs the Md<=9 masking
//  * one sync total; cooperative 256B-coalesced slab writeout
//  * resets its own cursors for the next graph replay
// ---------------------------------------------------------------------------
__global__ __launch_bounds__(256)
void splat_tiles_kernel(const float* __restrict__ half_shape,
                        float* __restrict__ out)
{
    const int b  = blockIdx.x;              // 4096 slabs
    const int s  = b & 3;                   // z-slab 0..3 (64 z each)
    const int ty = (b >> 2) & 31;
    const int tx = b >> 7;
    const int xb = tx * 8, yb = ty * 8;

    const int tid  = threadIdx.x;
    const int wid  = tid >> 5;
    const int lane = tid & 31;
    const int tzt  = s * 8 + wid;           // this warp's z-tile
    const int zbT  = tzt * 8;               // global z base of warp tile
    const int tile = (tx * NT8 + ty) * NT8 + tzt;

    __shared__ float4 sAcc[8][4][64];       // [warp][zpair][cell] = 32 KB

    // zero own region (warp-private; no sync needed before use)
    #pragma unroll
    for (int j = 0; j < 8; ++j)
        sAcc[wid][j >> 1][(j & 1) * 32 + lane] = make_float4(0.f,0.f,0.f,0.f);

    const float ihx = 1.0f / half_shape[0];
    const float ihy = 1.0f / half_shape[1];
    const float e   = 1.0f / half_shape[2];

    const int cnt = min(g_cursors8[tile], CAP8);
    if (lane == 0) g_cursors8[tile] = 0;    // self-reset for next replay
    const uint2* __restrict__ bucket = g_pairs8 + tile * CAP8;

    // lane -> cell within block: x = blk*4 + (lane>>3), y = lane&7
    const int lxi = lane >> 3;              // 0..3 within block
    const int lyi = lane & 7;
    const float fvy  = (float)(yb + lyi);
    const float fvx0 = (float)(xb + lxi);         // block 0
    const float fvx1 = (float)(xb + 4 + lxi);     // block 1

    const float h   = -0.72134752044448170f;   // -0.5 * log2(e)
    const float Lth = -6.49212768400033530f;   // 9 * h (Md<=9 <=> L>=Lth)

    for (int i = 0; i < cnt; ++i) {
        const uint2 pr = bucket[i];
        const unsigned bbp = pr.y;
        const int g = (int)pr.x;
        const float4 p0 = g_params[3*g+0];
        const float4 p1 = g_params[3*g+1];
        const float4 p2 = g_params[3*g+2];

        const int lx0 = bbp & 15,         lx1 = (bbp >> 4) & 15;
        const int ly0 = (bbp >> 8) & 15,  ly1 = (bbp >> 12) & 15;
        const int lz0 = (bbp >> 16) & 15, lz1 = (bbp >> 20) & 15;

        const float cx = p0.x, cy = p0.y, cz = p0.z, C00 = p0.w;
        const float C11 = p1.x, C22 = p1.y, S01 = p1.z, S02 = p1.w;
        const float S12 = p2.x;

        const float dy  = (fvy - cy) * ihy;
        const bool  yok = (lyi >= ly0) & (lyi <= ly1);

        // pair-uniform z quantities
        const int   z0e = lz0 & ~1;
        const float dzb = ((float)(zbT + z0e) - cz) * e;
        const float A   = C22 * e * e;
        const float hA  = h * A;
        const float dd  = 8.0f * hA;
        const float tC  = C22 * dzb * dzb;
        const int   tmax = (lz1 - z0e) >> 1;

        #pragma unroll
        for (int blk = 0; blk < 2; ++blk) {
            // warp-uniform block skip on x extent
            if (blk == 0) { if (lx0 > 3) continue; }
            else          { if (lx1 < 4) continue; }

            const int   x    = blk * 4 + lxi;
            const float fvx  = blk ? fvx1 : fvx0;
            const float dx   = (fvx - cx) * ihx;
            const bool  xyok = yok & (x >= lx0) & (x <= lx1);
            const float wr   = xyok ? p2.y : 0.0f;
            const float wi   = xyok ? p2.z : 0.0f;

            const float Bxy = fmaf(S02, dx, S12 * dy);
            const float Cxy = fmaf(fmaf(C00, dx, S01 * dy), dx,
                                   C11 * dy * dy);

            const float B = e * fmaf(2.0f * C22, dzb, Bxy);
            const float C = fmaf(Bxy, dzb, tC + Cxy);

            const float hB = h * B, hC = h * C;
            float L0  = hC;                         // z = z0e
            float L1  = hA + hB + hC;               // z = z0e+1
            float dL0 = 4.0f * hA + 2.0f * hB;
            float dL1 = 8.0f * hA + 2.0f * hB;

            float4* ap = &sAcc[wid][z0e >> 1][blk * 32 + lane];
            int zc = z0e;
            for (int t = 0; t <= tmax; ++t) {
                const bool v0 = (zc >= lz0);        // zc <= lz1 guaranteed
                const bool v1 = (zc + 1 <= lz1);
                const float Ls0 = (v0 && L0 >= Lth) ? L0 : -1000.0f;
                const float Ls1 = (v1 && L1 >= Lth) ? L1 : -1000.0f;
                float w0, w1;
                asm("ex2.approx.ftz.f32 %0, %1;" : "=f"(w0) : "f"(Ls0));
                asm("ex2.approx.ftz.f32 %0, %1;" : "=f"(w1) : "f"(Ls1));
                float4 v = *ap;
                v.x = fmaf(w0, wr, v.x);
                v.y = fmaf(w0, wi, v.y);
                v.z = fmaf(w1, wr, v.z);
                v.w = fmaf(w1, wi, v.w);
                *ap = v;
                ap += 64;
                L0 += dL0; dL0 += dd;
                L1 += dL1; dL1 += dd;
                zc += 2;
            }
        }
    }

    __syncthreads();

    // slab writeout: row (gx,gy) has 64 contiguous z. q = (vol,row,ch):
    // 16 consecutive tid cover one 256B run -> coalesced float4 stores.
    #pragma unroll
    for (int j = 0; j < 8; ++j) {
        const int q   = tid + 256 * j;      // 0..2047
        const int ch  = q & 15;             // z chunk of 4 (z = ch*4 in slab)
        const int row = (q >> 4) & 63;      // cell
        const int vol = q >> 10;            // 0..1
        const int w   = ch >> 1;
        const int zp0 = (ch & 1) * 2;
        const float4 a0 = sAcc[w][zp0 + 0][row];
        const float4 a1 = sAcc[w][zp0 + 1][row];
        const float4 v  = vol ? make_float4(a0.y, a0.w, a1.y, a1.w)
                              : make_float4(a0.x, a0.z, a1.x, a1.z);
        const int gx = xb + (row >> 3);
        const int gy = yb + (row & 7);
        const int gz = s * 64 + ch * 4;
        *(float4*)(out + vol * DHW_I + (gx * GH + gy) * GW + gz) = v;
    }
}

// ---------------------------------------------------------------------------
extern "C" void kernel_launch(void* const* d_in, const int* in_sizes, int n_in,
                              void* d_out, int out_size) {
    const float* center     = (const float*)d_in[0];
    const float* covinv     = (const float*)d_in[1];
    const float* dens_r     = (const float*)d_in[2];
    const float* dens_i     = (const float*)d_in[3];
    const float* radius     = (const float*)d_in[4];
    const float* half_shape = (const float*)d_in[5];

    float* out = (float*)d_out;
    const int N = in_sizes[2];

    scatter_kernel<<<(N + 63) / 64, 64>>>(center, covinv, dens_r, dens_i,
                                          radius, N);
    splat_tiles_kernel<<<4096, 256>>>(half_shape, out);
}

// round 13
// speedup vs baseline: 1.5215x; 1.5215x over previous
#include <cuda_runtime.h>
#include <cstdint>

#define GD 256
#define GH 256
#define GW 256
#define NT 16
#define TS 16
#define RWIN 6
#define DHW_I 16777216
#define NTILES 4096
#define CAP 512
#define MAXN 32768
#define CHUNK 64

// zero-initialized at module load; splat resets cursors each replay
__device__ int    g_cursors[NTILES];
__device__ uint2  g_pairs  [NTILES * CAP];
__device__ float4 g_params [MAXN * 3];  // {cx,cy,cz,C00},{C11,C22,S01,S02},{S12,wr,wi,-}

// exact unsigned division p/d for p<256, d in [1,16]: (p*magic)>>16
__constant__ unsigned c_magic[17] = {
    65536u, 65536u, 32768u, 21846u, 16384u, 13108u, 10923u, 9363u,
    8192u, 7282u, 6554u, 5958u, 5462u, 5042u, 4682u, 4370u, 4096u };

// ---------------------------------------------------------------------------
__device__ __forceinline__ bool gbounds(float cx, float cy, float cz, float r,
                                        int& x0, int& x1, int& y0, int& y1,
                                        int& z0, int& z1)
{
    const int bx = (int)floorf(cx);
    const int by = (int)floorf(cy);
    const int bz = (int)floorf(cz);
    x0 = max((int)floorf(cx - r), max(bx - RWIN, 0));
    x1 = min((int)ceilf (cx + r), min(bx + RWIN, GD - 1));
    y0 = max((int)floorf(cy - r), max(by - RWIN, 0));
    y1 = min((int)ceilf (cy + r), min(by + RWIN, GH - 1));
    z0 = max((int)floorf(cz - r), max(bz - RWIN, 0));
    z1 = min((int)ceilf (cz + r), min(bz + RWIN, GW - 1));
    return (x0 <= x1) && (y0 <= y1) && (z0 <= z1);
}

// ---------------------------------------------------------------------------
// Binning into 16^3-tile buckets + param packing.
// pr.x = gid; pr.y = tile-local bounds lx0,lx1,ly0,ly1,lz0,lz1 (4b each).
// ---------------------------------------------------------------------------
__global__ __launch_bounds__(64)
void scatter_kernel(const float* __restrict__ center,
                    const float* __restrict__ covinv,
                    const float* __restrict__ dens_r,
                    const float* __restrict__ dens_i,
                    const float* __restrict__ radius, int N)
{
    int g = blockIdx.x * blockDim.x + threadIdx.x;
    if (g >= N) return;

    const float cx = center[3*g+0], cy = center[3*g+1], cz = center[3*g+2];

    g_params[3*g+0] = make_float4(cx, cy, cz, covinv[9*g+0]);
    g_params[3*g+1] = make_float4(covinv[9*g+4], covinv[9*g+8],
                                  covinv[9*g+1] + covinv[9*g+3],
                                  covinv[9*g+2] + covinv[9*g+6]);
    g_params[3*g+2] = make_float4(covinv[9*g+5] + covinv[9*g+7],
                                  dens_r[g], dens_i[g], 0.0f);

    int x0, x1, y0, y1, z0, z1;
    if (!gbounds(cx, cy, cz, radius[g], x0, x1, y0, y1, z0, z1)) return;

    for (int tx = x0 >> 4; tx <= (x1 >> 4); ++tx) {
        const int xb = tx * TS;
        const unsigned lx0 = (unsigned)max(x0 - xb, 0);
        const unsigned lx1 = (unsigned)min(x1 - xb, TS - 1);
        for (int ty = y0 >> 4; ty <= (y1 >> 4); ++ty) {
            const int yb = ty * TS;
            const unsigned ly0 = (unsigned)max(y0 - yb, 0);
            const unsigned ly1 = (unsigned)min(y1 - yb, TS - 1);
            for (int tz = z0 >> 4; tz <= (z1 >> 4); ++tz) {
                const int zb = tz * TS;
                const unsigned lz0 = (unsigned)max(z0 - zb, 0);
                const unsigned lz1 = (unsigned)min(z1 - zb, TS - 1);
                const unsigned bb = lx0 | (lx1 << 4) | (ly0 << 8) |
                                    (ly1 << 12) | (lz0 << 16) | (lz1 << 20);
                const int tile = (tx * NT + ty) * NT + tz;
                const int slot = atomicAdd(&g_cursors[tile], 1);
                if (slot < CAP)
                    g_pairs[tile * CAP + slot] = make_uint2((unsigned)g, bb);
            }
        }
    }
}

// ---------------------------------------------------------------------------
// One 256-thread CTA per 16^3 tile. WARP w exclusively owns z-slice
// {2w, 2w+1}: sAcc[w][cell] = {r(2w), i(2w), r(2w+1), i(2w+1)} is
// warp-private -> no races, no xy windows, no idle-lane z-loops.
//  * per pair, each z-overlapping warp runs a COMPACTED xy loop
//    (p = lane .. nxy step 32; exact magic division p -> (ox,oy)):
//    ~100% lane efficiency, xy masks eliminated entirely
//  * z-validity masks are warp-uniform, folded into wr/wi via FSEL
//  * per cell: L0/L1 via 4 FMA from pair-uniform constants, 2 FSEL + 2 ex2,
//    one float4 LDS/STS RMW covers both z
//  * sAcc padded [8][257] -> conflict-free main loop AND transpose writeout
//  * coalesced float4 writeout; cursor self-reset for next graph replay
// ---------------------------------------------------------------------------
__global__ __launch_bounds__(256)
void splat_tiles_kernel(const float* __restrict__ half_shape,
                        float* __restrict__ out)
{
    const int b  = blockIdx.x;
    const int tz = b & 15, ty = (b >> 4) & 15, tx = b >> 8;
    const int xb = tx * TS, yb = ty * TS, zb = tz * TS;

    const int tid  = threadIdx.x;
    const int wid  = tid >> 5;
    const int lane = tid & 31;
    const int zlo  = 2 * wid;              // warp-owned z (tile-local)
    const int zhi  = zlo + 1;

    __shared__ float4   sAcc[8][257];      // padded: conflict-free transpose
    __shared__ float4   sp4[CHUNK * 3];
    __shared__ unsigned sbnd[CHUNK];
    __shared__ int      scnt;

    // zero own slice (warp-private; no pre-sync needed)
    #pragma unroll
    for (int j = 0; j < 8; ++j)
        sAcc[wid][j * 32 + lane] = make_float4(0.f, 0.f, 0.f, 0.f);

    if (tid == 0) {
        scnt = min(g_cursors[b], CAP);
        g_cursors[b] = 0;                  // self-reset for next replay
    }
    __syncthreads();

    const float ihx = 1.0f / half_shape[0];
    const float ihy = 1.0f / half_shape[1];
    const float e   = 1.0f / half_shape[2];

    const int cnt = scnt;
    const uint2* __restrict__ bucket = g_pairs + b * CAP;

    const float h   = -0.72134752044448170f;   // -0.5 * log2(e)
    const float Lth = -6.49212768400033530f;   // 9*h  (Md<=9 <=> L>=Lth)
    const float he  = h * e;
    const float zgf = (float)(zb + zlo);        // this warp's global z

    for (int base = 0; base < cnt; base += CHUNK) {
        const int n = min(cnt - base, CHUNK);
        __syncthreads();
        if (tid < n) {
            const uint2 pr = bucket[base + tid];
            const int g = (int)pr.x;
            sp4[3*tid+0] = g_params[3*g+0];
            sp4[3*tid+1] = g_params[3*g+1];
            sp4[3*tid+2] = g_params[3*g+2];
            sbnd[tid] = pr.y;
        }
        __syncthreads();

        for (int i = 0; i < n; ++i) {
            const unsigned bbp = sbnd[i];
            const int lz0 = (bbp >> 16) & 15, lz1 = (bbp >> 20) & 15;
            if (zhi < lz0 || zlo > lz1) continue;   // warp z-slice skip

            const int lx0 = bbp & 15,        lx1 = (bbp >> 4) & 15;
            const int ly0 = (bbp >> 8) & 15, ly1 = (bbp >> 12) & 15;
            const int nyp = ly1 - ly0 + 1;
            const int nxy = (lx1 - lx0 + 1) * nyp;
            const unsigned magic = c_magic[nyp];

            const float4 p0 = sp4[3*i+0];
            const float4 p1 = sp4[3*i+1];
            const float4 p2 = sp4[3*i+2];
            const float cx = p0.x, cy = p0.y, cz = p0.z, C00 = p0.w;
            const float C11 = p1.x, C22 = p1.y, S01 = p1.z, S02 = p1.w;
            const float S12 = p2.x;

            // warp-uniform z validity folded into weights
            const bool v0 = (zlo >= lz0) & (zlo <= lz1);
            const bool v1 = (zhi >= lz0) & (zhi <= lz1);
            const float wr0 = v0 ? p2.y : 0.0f;
            const float wi0 = v0 ? p2.z : 0.0f;
            const float wr1 = v1 ? p2.y : 0.0f;
            const float wi1 = v1 ? p2.z : 0.0f;

            // pair+warp uniform z constants
            const float dz0 = (zgf - cz) * e;
            const float hdz = h * dz0;
            const float hCz = h * C22 * dz0 * dz0;
            const float hk1 = h * C22 * e * fmaf(2.0f, dz0, e);

            const float dxb = ((float)(xb + lx0) - cx) * ihx;
            const float dyb = ((float)(yb + ly0) - cy) * ihy;

            for (int p = lane; p < nxy; p += 32) {
                const int ox = (int)(((unsigned)p * magic) >> 16);
                const int oy = p - ox * nyp;

                const float dx = fmaf((float)ox, ihx, dxb);
                const float dy = fmaf((float)oy, ihy, dyb);

                const float Bxy = fmaf(S02, dx, S12 * dy);
                const float Cxy = fmaf(fmaf(C00, dx, S01 * dy), dx,
                                       C11 * dy * dy);

                const float L0 = fmaf(hdz, Bxy, fmaf(h, Cxy, hCz));
                const float L1 = fmaf(he, Bxy, L0 + hk1);

                const float Ls0 = (L0 >= Lth) ? L0 : -1000.0f;
                const float Ls1 = (L1 >= Lth) ? L1 : -1000.0f;
                float w0, w1;
                asm("ex2.approx.ftz.f32 %0, %1;" : "=f"(w0) : "f"(Ls0));
                asm("ex2.approx.ftz.f32 %0, %1;" : "=f"(w1) : "f"(Ls1));

                const int cell = (lx0 + ox) * 16 + (ly0 + oy);
                float4 v = sAcc[wid][cell];
                v.x = fmaf(w0, wr0, v.x);
                v.y = fmaf(w0, wi0, v.y);
                v.z = fmaf(w1, wr1, v.z);
                v.w = fmaf(w1, wi1, v.w);
                sAcc[wid][cell] = v;
            }
        }
    }

    __syncthreads();

    // writeout: q=(cell c, z-quad k): lanes 0-3 share c (64B contiguous z),
    // quad z in {4k..4k+3} = slices 2k (z 4k,4k+1) and 2k+1 (z 4k+2,4k+3).
    #pragma unroll
    for (int j = 0; j < 4; ++j) {
        const int q = tid + 256 * j;        // 0..1023
        const int c = q >> 2;               // cell 0..255
        const int k = q & 3;                // z quad
        const float4 a  = sAcc[2*k + 0][c];
        const float4 bq = sAcc[2*k + 1][c];
        const int gx = xb + (c >> 4);
        const int gy = yb + (c & 15);
        const int idx = (gx * GH + gy) * GW + zb + 4 * k;
        *(float4*)(out + idx)         = make_float4(a.x, a.z, bq.x, bq.z);
        *(float4*)(out + idx + DHW_I) = make_float4(a.y, a.w, bq.y, bq.w);
    }
}

// ---------------------------------------------------------------------------
extern "C" void kernel_launch(void* const* d_in, const int* in_sizes, int n_in,
                              void* d_out, int out_size) {
    const float* center     = (const float*)d_in[0];
    const float* covinv     = (const float*)d_in[1];
    const float* dens_r     = (const float*)d_in[2];
    const float* dens_i     = (const float*)d_in[3];
    const float* radius     = (const float*)d_in[4];
    const float* half_shape = (const float*)d_in[5];

    float* out = (float*)d_out;
    const int N = in_sizes[2];

    scatter_kernel<<<(N + 63) / 64, 64>>>(center, covinv, dens_r, dens_i,
                                          radius, N);
    splat_tiles_kernel<<<NTILES, 256>>>(half_shape, out);
}